// round 2
// baseline (speedup 1.0000x reference)
#include <cuda_runtime.h>

#define NN 131072
#define EE 2097152
#define GB 8
#define CWD 64

// ---------------- static device scratch ----------------
__device__ int d_cnt[NN];
__device__ int d_rowptr[NN + 1];
__device__ int d_cursor[NN];
__device__ int d_csr_src[EE];
__device__ int d_blocksums[128];
__device__ float d_hA[NN * CWD];
__device__ float d_hB[NN * CWD];
__device__ float d_xw[NN * CWD];
__device__ float d_score[NN];
__device__ float d_dis[NN];
__device__ int d_c2oA[NN];
__device__ int d_c2oB[NN];
__device__ int d_o2c[NN];
__device__ int d_oldidx[NN];
__device__ unsigned d_thresh[GB];
__device__ int d_quota[GB];
__device__ int d_ctr[GB];
__device__ int d_eq[GB];
__device__ float d_ro[4 * GB * 2 * CWD];
__device__ float d_WT[4][CWD * CWD];  // transposed Wl2, Wr2, W4, W5

__device__ __forceinline__ unsigned fkey(float f) {
    unsigned b = __float_as_uint(f);
    return (b & 0x80000000u) ? ~b : (b | 0x80000000u);
}

// ---------------- CSR build ----------------
__global__ void init_kernel() {
    int i = blockIdx.x * blockDim.x + threadIdx.x;
    if (i < NN) { d_cnt[i] = 0; d_c2oA[i] = i; }
}

__global__ void hist_kernel(const int* __restrict__ dst) {
    int e = blockIdx.x * blockDim.x + threadIdx.x;
    if (e < EE) atomicAdd(&d_cnt[dst[e]], 1);
}

__global__ void __launch_bounds__(1024, 1) scan1_kernel() {
    __shared__ int s[1024];
    int t = threadIdx.x, i = blockIdx.x * 1024 + t;
    int v = d_cnt[i];
    s[t] = v; __syncthreads();
    for (int off = 1; off < 1024; off <<= 1) {
        int tmp = (t >= off) ? s[t - off] : 0;
        __syncthreads();
        s[t] += tmp;
        __syncthreads();
    }
    d_rowptr[i] = s[t] - v;
    if (t == 1023) d_blocksums[blockIdx.x] = s[t];
}

__global__ void scan2_kernel() {
    __shared__ int s[128];
    int t = threadIdx.x;
    int v = d_blocksums[t];
    s[t] = v; __syncthreads();
    for (int off = 1; off < 128; off <<= 1) {
        int tmp = (t >= off) ? s[t - off] : 0;
        __syncthreads();
        s[t] += tmp;
        __syncthreads();
    }
    d_blocksums[t] = s[t] - v;  // exclusive
}

__global__ void scan3_kernel() {
    int i = blockIdx.x * blockDim.x + threadIdx.x;
    if (i < NN) {
        int r = d_rowptr[i] + d_blocksums[i >> 10];
        d_rowptr[i] = r;
        d_cursor[i] = r;
        if (i == 0) d_rowptr[NN] = EE;
    }
}

__global__ void scatter_kernel(const int* __restrict__ src, const int* __restrict__ dst) {
    int e = blockIdx.x * blockDim.x + threadIdx.x;
    if (e < EE) {
        int p = atomicAdd(&d_cursor[dst[e]], 1);
        d_csr_src[p] = src[e];
    }
}

__global__ void transpose_kernel(const float* __restrict__ W, int slot) {
    int i = blockIdx.x * blockDim.x + threadIdx.x;
    if (i < CWD * CWD) {
        int r = i >> 6, c = i & 63;
        d_WT[slot][c * 64 + r] = W[i];
    }
}

// ---------------- conv1: SAGE (2 -> 64), warp per node, all edges alive ----------------
__global__ void conv1_kernel(const float* __restrict__ x,
                             const float* __restrict__ Wl, const float* __restrict__ bl,
                             const float* __restrict__ Wr, const float* __restrict__ wp) {
    int gw = (blockIdx.x * blockDim.x + threadIdx.x) >> 5;
    if (gw >= NN) return;
    int lane = threadIdx.x & 31;
    int row = d_rowptr[gw], end = d_rowptr[gw + 1];
    float a0 = 0.f, a1 = 0.f;
    for (int e = row + lane; e < end; e += 32) {
        int s = d_csr_src[e];
        a0 += x[2 * s];
        a1 += x[2 * s + 1];
    }
    for (int o = 16; o; o >>= 1) {
        a0 += __shfl_xor_sync(0xffffffffu, a0, o);
        a1 += __shfl_xor_sync(0xffffffffu, a1, o);
    }
    float deg = (float)(end - row);
    float inv = deg > 0.f ? 1.f / deg : 0.f;
    float m0 = a0 * inv, m1 = a1 * inv;
    float x0 = x[2 * gw], x1 = x[2 * gw + 1];
    int d0 = lane, d1 = lane + 32;
    float o0 = Wl[d0 * 2] * m0 + Wl[d0 * 2 + 1] * m1 + bl[d0] + Wr[d0 * 2] * x0 + Wr[d0 * 2 + 1] * x1;
    float o1 = Wl[d1 * 2] * m0 + Wl[d1 * 2 + 1] * m1 + bl[d1] + Wr[d1 * 2] * x0 + Wr[d1 * 2 + 1] * x1;
    o0 = fmaxf(o0, 0.f); o1 = fmaxf(o1, 0.f);
    d_hA[gw * 64 + d0] = o0;
    d_hA[gw * 64 + d1] = o1;
    float w0 = wp[d0], w1 = wp[d1];
    float sd = o0 * w0 + o1 * w1, nw = w0 * w0 + w1 * w1;
    for (int o = 16; o; o >>= 1) {
        sd += __shfl_xor_sync(0xffffffffu, sd, o);
        nw += __shfl_xor_sync(0xffffffffu, nw, o);
    }
    if (lane == 0) d_score[gw] = tanhf(sd * rsqrtf(nw));
}

// ---------------- radix select (per-graph exact k-th largest) ----------------
__global__ void select_kernel(int m, int k) {
    __shared__ unsigned hist[256];
    __shared__ unsigned s_pref;
    __shared__ int s_rem;
    int b = blockIdx.x, t = threadIdx.x;
    int base = b * m;
    if (t == 0) { s_pref = 0u; s_rem = k; }
    __syncthreads();
    for (int p = 3; p >= 0; p--) {
        hist[t] = 0;
        __syncthreads();
        unsigned pref = s_pref;
        int hs = (p + 1) * 8;
        for (int i = t; i < m; i += 256) {
            unsigned u = fkey(d_score[base + i]);
            bool cand = (p == 3) || ((u >> hs) == (pref >> hs));
            if (cand) atomicAdd(&hist[(u >> (p * 8)) & 255], 1u);
        }
        __syncthreads();
        if (t == 0) {
            int rem = s_rem;
            unsigned c = 0;
            for (int bb = 255; bb >= 0; bb--) {
                if (c + hist[bb] >= (unsigned)rem) {
                    s_pref = pref | ((unsigned)bb << (p * 8));
                    s_rem = rem - (int)c;
                    break;
                }
                c += hist[bb];
            }
        }
        __syncthreads();
    }
    if (t == 0) {
        d_thresh[b] = s_pref;
        d_quota[b] = s_rem;
        d_ctr[b] = 0;
        d_eq[b] = 0;
    }
}

__global__ void compact_kernel(int shift, int k, int flip) {
    int c = blockIdx.x * blockDim.x + threadIdx.x;
    int b = c >> shift;
    unsigned u = fkey(d_score[c]);
    unsigned th = d_thresh[b];
    const int* oldm = flip ? d_c2oB : d_c2oA;
    int* newm = flip ? d_c2oA : d_c2oB;
    bool keep = u > th;
    if (!keep && u == th) keep = (atomicAdd(&d_eq[b], 1) < d_quota[b]);
    int orig = oldm[c];
    if (keep) {
        int slot = atomicAdd(&d_ctr[b], 1);
        int nc = b * k + slot;
        newm[nc] = orig;
        d_o2c[orig] = nc;
        d_oldidx[nc] = c;
    } else {
        d_o2c[orig] = -1;
    }
}

__global__ void copy_kernel(int k) {
    int gw = (blockIdx.x * blockDim.x + threadIdx.x) >> 5;
    if (gw >= GB * k) return;
    int lane = threadIdx.x & 31;
    int oldc = d_oldidx[gw];
    float v = d_score[oldc];
    d_hB[gw * 64 + lane] = d_hA[oldc * 64 + lane] * v;
    d_hB[gw * 64 + lane + 32] = d_hA[oldc * 64 + lane + 32] * v;
}

// ---------------- readout: per-graph max + mean over k nodes ----------------
__global__ void __launch_bounds__(1024, 1) readout_kernel(int k, int stage) {
    __shared__ float smx[1024];
    __shared__ float ssm[1024];
    int t = threadIdx.x, b = blockIdx.x;
    int r0 = t >> 6, d = t & 63;
    float mx = -3.4e38f, sm = 0.f;
    for (int r = r0; r < k; r += 16) {
        float v = d_hB[(b * k + r) * 64 + d];
        mx = fmaxf(mx, v);
        sm += v;
    }
    smx[t] = mx; ssm[t] = sm;
    __syncthreads();
    for (int s = 8; s >= 1; s >>= 1) {
        if (r0 < s) {
            smx[t] = fmaxf(smx[t], smx[t + s * 64]);
            ssm[t] += ssm[t + s * 64];
        }
        __syncthreads();
    }
    if (r0 == 0) {
        d_ro[stage * 1024 + b * 128 + d] = smx[t];
        d_ro[stage * 1024 + b * 128 + 64 + d] = ssm[t] / (float)k;
    }
}

// ---------------- SAGE conv2 (64 -> 64), warp per current node ----------------
__global__ void __launch_bounds__(256) sage_kernel(int M, int sel, const float* __restrict__ bl,
                            const float* __restrict__ wp) {
    int gw = (blockIdx.x * blockDim.x + threadIdx.x) >> 5;
    if (gw >= M) return;
    int lane = threadIdx.x & 31;
    const int* c2o = sel ? d_c2oB : d_c2oA;
    int o = c2o[gw];
    int row = d_rowptr[o], end = d_rowptr[o + 1];
    int d0 = lane, d1 = lane + 32;
    float a0 = 0.f, a1 = 0.f;
    int cnt = 0;
    for (int base = row; base < end; base += 32) {
        int e = base + lane;
        int sc = -1;
        if (e < end) sc = d_o2c[d_csr_src[e]];
        int nb = min(32, end - base);
        for (int j = 0; j < nb; j++) {
            int scj = __shfl_sync(0xffffffffu, sc, j);
            if (scj >= 0) {
                cnt++;
                a0 += d_hB[scj * 64 + d0];
                a1 += d_hB[scj * 64 + d1];
            }
        }
    }
    float invc = cnt ? 1.f / (float)cnt : 0.f;
    float m0 = a0 * invc, m1 = a1 * invc;
    float h0 = d_hB[gw * 64 + d0], h1 = d_hB[gw * 64 + d1];
    float o0 = bl[d0], o1 = bl[d1];
    const float* WlT = d_WT[0];
    const float* WrT = d_WT[1];
    for (int j = 0; j < 32; j++) {
        float mj = __shfl_sync(0xffffffffu, m0, j);
        float hj = __shfl_sync(0xffffffffu, h0, j);
        o0 += WlT[j * 64 + d0] * mj + WrT[j * 64 + d0] * hj;
        o1 += WlT[j * 64 + d1] * mj + WrT[j * 64 + d1] * hj;
    }
    for (int j = 0; j < 32; j++) {
        float mj = __shfl_sync(0xffffffffu, m1, j);
        float hj = __shfl_sync(0xffffffffu, h1, j);
        o0 += WlT[(j + 32) * 64 + d0] * mj + WrT[(j + 32) * 64 + d0] * hj;
        o1 += WlT[(j + 32) * 64 + d1] * mj + WrT[(j + 32) * 64 + d1] * hj;
    }
    o0 = fmaxf(o0, 0.f); o1 = fmaxf(o1, 0.f);
    d_hA[gw * 64 + d0] = o0;
    d_hA[gw * 64 + d1] = o1;
    float w0 = wp[d0], w1 = wp[d1];
    float sd = o0 * w0 + o1 * w1, nw = w0 * w0 + w1 * w1;
    for (int s = 16; s; s >>= 1) {
        sd += __shfl_xor_sync(0xffffffffu, sd, s);
        nw += __shfl_xor_sync(0xffffffffu, nw, s);
    }
    if (lane == 0) d_score[gw] = tanhf(sd * rsqrtf(nw));
}

// ---------------- GCN helpers ----------------
__global__ void __launch_bounds__(256) xw_kernel(int M, int slot) {
    int gw = (blockIdx.x * blockDim.x + threadIdx.x) >> 5;
    if (gw >= M) return;
    int lane = threadIdx.x & 31;
    int d0 = lane, d1 = lane + 32;
    float h0 = d_hB[gw * 64 + d0], h1 = d_hB[gw * 64 + d1];
    float a0 = 0.f, a1 = 0.f;
    const float* WT = d_WT[slot];
    for (int j = 0; j < 32; j++) {
        float hj = __shfl_sync(0xffffffffu, h0, j);
        a0 += WT[j * 64 + d0] * hj;
        a1 += WT[j * 64 + d1] * hj;
    }
    for (int j = 0; j < 32; j++) {
        float hj = __shfl_sync(0xffffffffu, h1, j);
        a0 += WT[(j + 32) * 64 + d0] * hj;
        a1 += WT[(j + 32) * 64 + d1] * hj;
    }
    d_xw[gw * 64 + d0] = a0;
    d_xw[gw * 64 + d1] = a1;
}

__global__ void deg_kernel(int M, int sel) {
    int c = blockIdx.x * blockDim.x + threadIdx.x;
    if (c >= M) return;
    const int* c2o = sel ? d_c2oB : d_c2oA;
    int o = c2o[c];
    int cnt = 0;
    int end = d_rowptr[o + 1];
    for (int e = d_rowptr[o]; e < end; e++)
        if (d_o2c[d_csr_src[e]] >= 0) cnt++;
    d_dis[c] = rsqrtf(1.f + (float)cnt);
}

__global__ void __launch_bounds__(256) gcn_kernel(int M, int slot, const float* __restrict__ bias,
                           const float* __restrict__ wp, int sel) {
    int gw = (blockIdx.x * blockDim.x + threadIdx.x) >> 5;
    if (gw >= M) return;
    int lane = threadIdx.x & 31;
    const int* c2o = sel ? d_c2oB : d_c2oA;
    int o = c2o[gw];
    float dd = d_dis[gw];
    int row = d_rowptr[o], end = d_rowptr[o + 1];
    int d0 = lane, d1 = lane + 32;
    float a0 = 0.f, a1 = 0.f;
    for (int base = row; base < end; base += 32) {
        int e = base + lane;
        int sc = -1;
        float ds = 0.f;
        if (e < end) {
            sc = d_o2c[d_csr_src[e]];
            if (sc >= 0) ds = d_dis[sc];
        }
        int nb = min(32, end - base);
        for (int j = 0; j < nb; j++) {
            int scj = __shfl_sync(0xffffffffu, sc, j);
            float dsj = __shfl_sync(0xffffffffu, ds, j);
            if (scj >= 0) {
                a0 += d_xw[scj * 64 + d0] * dsj;
                a1 += d_xw[scj * 64 + d1] * dsj;
            }
        }
    }
    a0 *= dd; a1 *= dd;
    float o0 = a0 + d_xw[gw * 64 + d0] * dd * dd + bias[d0];
    float o1 = a1 + d_xw[gw * 64 + d1] * dd * dd + bias[d1];
    o0 = fmaxf(o0, 0.f); o1 = fmaxf(o1, 0.f);
    d_hA[gw * 64 + d0] = o0;
    d_hA[gw * 64 + d1] = o1;
    float w0 = wp[d0], w1 = wp[d1];
    float sd = o0 * w0 + o1 * w1, nw = w0 * w0 + w1 * w1;
    for (int s = 16; s; s >>= 1) {
        sd += __shfl_xor_sync(0xffffffffu, sd, s);
        nw += __shfl_xor_sync(0xffffffffu, nw, s);
    }
    if (lane == 0) d_score[gw] = tanhf(sd * rsqrtf(nw));
}

// ---------------- final MLP + softmax ----------------
__global__ void __launch_bounds__(1024, 1) mlp_kernel(const float* __restrict__ Wa, const float* __restrict__ ba,
                           const float* __restrict__ Wb, const float* __restrict__ bb,
                           const float* __restrict__ Wc, const float* __restrict__ bc,
                           float* __restrict__ out) {
    __shared__ float zs[1024];
    __shared__ float za[1024];
    __shared__ float zb[512];
    __shared__ float zc[2048];
    int t = threadIdx.x;
    zs[t] = d_ro[t] + d_ro[1024 + t] + d_ro[2048 + t] + d_ro[3072 + t];
    __syncthreads();
    {
        int b = t >> 7, o = t & 127;
        float a = ba[o];
        const float* w = Wa + o * 128;
        const float* z = zs + b * 128;
        for (int j = 0; j < 128; j++) a += w[j] * z[j];
        za[t] = fmaxf(a, 0.f);
    }
    __syncthreads();
    if (t < 512) {
        int b = t >> 6, o = t & 63;
        float a = bb[o];
        for (int j = 0; j < 128; j++) a += Wb[o * 128 + j] * za[b * 128 + j];
        zb[t] = fmaxf(a, 0.f);
    }
    __syncthreads();
    for (int q = t; q < 2048; q += 1024) {
        int b = q >> 8, o = q & 255;
        float a = bc[o];
        for (int j = 0; j < 64; j++) a += Wc[o * 64 + j] * zb[b * 64 + j];
        zc[q] = a;
    }
    __syncthreads();
    int w = t >> 5, lane = t & 31;
    if (w < 8) {
        float mx = -3.4e38f;
        for (int i = lane; i < 256; i += 32) mx = fmaxf(mx, zc[w * 256 + i]);
        for (int o = 16; o; o >>= 1) mx = fmaxf(mx, __shfl_xor_sync(0xffffffffu, mx, o));
        float s = 0.f;
        for (int i = lane; i < 256; i += 32) {
            float e = expf(zc[w * 256 + i] - mx);
            zc[w * 256 + i] = e;
            s += e;
        }
        for (int o = 16; o; o >>= 1) s += __shfl_xor_sync(0xffffffffu, s, o);
        float inv = 1.f / s;
        for (int i = lane; i < 256; i += 32) out[w * 256 + i] = zc[w * 256 + i] * inv;
    }
}

// ---------------- launch ----------------
extern "C" void kernel_launch(void* const* d_in, const int* in_sizes, int n_in,
                              void* d_out, int out_size) {
    const float* x = (const float*)d_in[0];
    const int* ei = (const int*)d_in[1];
    const int* src = ei;
    const int* dst = ei + EE;
    const float* Wl1 = (const float*)d_in[2];
    const float* bl1 = (const float*)d_in[3];
    const float* Wr1 = (const float*)d_in[4];
    const float* Wl2 = (const float*)d_in[5];
    const float* bl2 = (const float*)d_in[6];
    const float* Wr2 = (const float*)d_in[7];
    const float* W4  = (const float*)d_in[8];
    const float* b4  = (const float*)d_in[9];
    const float* W5  = (const float*)d_in[10];
    const float* b5  = (const float*)d_in[11];
    const float* wp1 = (const float*)d_in[12];
    const float* wp2 = (const float*)d_in[13];
    const float* wp4 = (const float*)d_in[14];
    const float* wp5 = (const float*)d_in[15];
    const float* Wa  = (const float*)d_in[16];
    const float* ba  = (const float*)d_in[17];
    const float* Wb  = (const float*)d_in[18];
    const float* bb  = (const float*)d_in[19];
    const float* Wc  = (const float*)d_in[20];
    const float* bc  = (const float*)d_in[21];
    float* out = (float*)d_out;

    // CSR build
    init_kernel<<<NN / 256, 256>>>();
    hist_kernel<<<EE / 256, 256>>>(dst);
    scan1_kernel<<<128, 1024>>>();
    scan2_kernel<<<1, 128>>>();
    scan3_kernel<<<NN / 256, 256>>>();
    scatter_kernel<<<EE / 256, 256>>>(src, dst);
    transpose_kernel<<<16, 256>>>(Wl2, 0);
    transpose_kernel<<<16, 256>>>(Wr2, 1);
    transpose_kernel<<<16, 256>>>(W4, 2);
    transpose_kernel<<<16, 256>>>(W5, 3);

    // stage 1: SAGE1 on all N nodes, pool 16384 -> 8192
    conv1_kernel<<<NN / 8, 256>>>(x, Wl1, bl1, Wr1, wp1);
    select_kernel<<<GB, 256>>>(16384, 8192);
    compact_kernel<<<(GB * 16384) / 256, 256>>>(14, 8192, 0);
    copy_kernel<<<(GB * 8192) / 8, 256>>>(8192);
    readout_kernel<<<GB, 1024>>>(8192, 0);

    // stage 2: SAGE2 on 65536 nodes, pool 8192 -> 4096
    sage_kernel<<<65536 / 8, 256>>>(65536, 1, bl2, wp2);
    select_kernel<<<GB, 256>>>(8192, 4096);
    compact_kernel<<<(GB * 8192) / 256, 256>>>(13, 4096, 1);
    copy_kernel<<<(GB * 4096) / 8, 256>>>(4096);
    readout_kernel<<<GB, 1024>>>(4096, 1);

    // stage 3: GCN on 32768 nodes, pool 4096 -> 2048
    xw_kernel<<<32768 / 8, 256>>>(32768, 2);
    deg_kernel<<<32768 / 256, 256>>>(32768, 0);
    gcn_kernel<<<32768 / 8, 256>>>(32768, 2, b4, wp4, 0);
    select_kernel<<<GB, 256>>>(4096, 2048);
    compact_kernel<<<(GB * 4096) / 256, 256>>>(12, 2048, 0);
    copy_kernel<<<(GB * 2048) / 8, 256>>>(2048);
    readout_kernel<<<GB, 1024>>>(2048, 2);

    // stage 4: GCN on 16384 nodes, pool 2048 -> 1024
    xw_kernel<<<16384 / 8, 256>>>(16384, 3);
    deg_kernel<<<16384 / 256, 256>>>(16384, 1);
    gcn_kernel<<<16384 / 8, 256>>>(16384, 3, b5, wp5, 1);
    select_kernel<<<GB, 256>>>(2048, 1024);
    compact_kernel<<<(GB * 2048) / 256, 256>>>(11, 1024, 1);
    copy_kernel<<<(GB * 1024) / 8, 256>>>(1024);
    readout_kernel<<<GB, 1024>>>(1024, 3);

    // final MLP + softmax
    mlp_kernel<<<1, 1024>>>(Wa, ba, Wb, bb, Wc, bc, out);
}

// round 3
// speedup vs baseline: 1.1105x; 1.1105x over previous
#include <cuda_runtime.h>

#define NN 131072
#define EE 2097152
#define GB 8
#define CWD 64

// ---------------- static device scratch ----------------
__device__ int d_cnt[NN];
__device__ int d_rowptr[NN + 1];
__device__ int d_cursor[NN];
__device__ int d_csr_src[EE];
__device__ int d_blocksums[128];
__device__ float d_hA[NN * CWD];
__device__ float d_hB[NN * CWD];
__device__ float d_xw[NN * CWD];
__device__ float d_score[NN];
__device__ float d_dis[NN];
__device__ int d_c2oA[NN];
__device__ int d_c2oB[NN];
__device__ int d_o2c[NN];
__device__ int d_oldidx[NN];
__device__ unsigned d_thresh[GB];
__device__ int d_quota[GB];
__device__ int d_ctr[GB];
__device__ int d_eq[GB];
__device__ unsigned d_romax[4 * GB * CWD];  // fkey-encoded per-dim max
__device__ float d_rosum[4 * GB * CWD];     // per-dim sum
__device__ float d_WT[4][CWD * CWD];        // transposed Wl2, Wr2, W4, W5

__device__ __forceinline__ unsigned fkey(float f) {
    unsigned b = __float_as_uint(f);
    return (b & 0x80000000u) ? ~b : (b | 0x80000000u);
}
__device__ __forceinline__ float unfkey(unsigned u) {
    unsigned b = (u & 0x80000000u) ? (u & 0x7fffffffu) : ~u;
    return __uint_as_float(b);
}

// ---------------- CSR build ----------------
__global__ void init_kernel() {
    int i = blockIdx.x * blockDim.x + threadIdx.x;
    if (i < NN) { d_cnt[i] = 0; d_c2oA[i] = i; }
    if (i < 4 * GB * CWD) { d_romax[i] = 0u; d_rosum[i] = 0.f; }
}

__global__ void hist_kernel(const int* __restrict__ dst) {
    int e = blockIdx.x * blockDim.x + threadIdx.x;
    if (e < EE) atomicAdd(&d_cnt[dst[e]], 1);
}

__global__ void __launch_bounds__(1024, 1) scan1_kernel() {
    __shared__ int s[1024];
    int t = threadIdx.x, i = blockIdx.x * 1024 + t;
    int v = d_cnt[i];
    s[t] = v; __syncthreads();
    for (int off = 1; off < 1024; off <<= 1) {
        int tmp = (t >= off) ? s[t - off] : 0;
        __syncthreads();
        s[t] += tmp;
        __syncthreads();
    }
    d_rowptr[i] = s[t] - v;
    if (t == 1023) d_blocksums[blockIdx.x] = s[t];
}

__global__ void scan2_kernel() {
    __shared__ int s[128];
    int t = threadIdx.x;
    int v = d_blocksums[t];
    s[t] = v; __syncthreads();
    for (int off = 1; off < 128; off <<= 1) {
        int tmp = (t >= off) ? s[t - off] : 0;
        __syncthreads();
        s[t] += tmp;
        __syncthreads();
    }
    d_blocksums[t] = s[t] - v;  // exclusive
}

__global__ void scan3_kernel() {
    int i = blockIdx.x * blockDim.x + threadIdx.x;
    if (i < NN) {
        int r = d_rowptr[i] + d_blocksums[i >> 10];
        d_rowptr[i] = r;
        d_cursor[i] = r;
        if (i == 0) d_rowptr[NN] = EE;
    }
}

__global__ void scatter_kernel(const int* __restrict__ src, const int* __restrict__ dst) {
    int e = blockIdx.x * blockDim.x + threadIdx.x;
    if (e < EE) {
        int p = atomicAdd(&d_cursor[dst[e]], 1);
        d_csr_src[p] = src[e];
    }
}

__global__ void transpose_all_kernel(const float* __restrict__ Wl2, const float* __restrict__ Wr2,
                                     const float* __restrict__ W4, const float* __restrict__ W5) {
    int id = blockIdx.x * blockDim.x + threadIdx.x;
    int slot = id >> 12;
    int i = id & 4095;
    const float* W = slot == 0 ? Wl2 : slot == 1 ? Wr2 : slot == 2 ? W4 : W5;
    int r = i >> 6, c = i & 63;
    d_WT[slot][c * 64 + r] = W[i];
}

// ---------------- conv1: SAGE (2 -> 64), warp per node, all edges alive ----------------
__global__ void conv1_kernel(const float* __restrict__ x,
                             const float* __restrict__ Wl, const float* __restrict__ bl,
                             const float* __restrict__ Wr, const float* __restrict__ wp) {
    int gw = (blockIdx.x * blockDim.x + threadIdx.x) >> 5;
    if (gw >= NN) return;
    int lane = threadIdx.x & 31;
    int row = d_rowptr[gw], end = d_rowptr[gw + 1];
    float a0 = 0.f, a1 = 0.f;
    for (int e = row + lane; e < end; e += 32) {
        int s = d_csr_src[e];
        a0 += x[2 * s];
        a1 += x[2 * s + 1];
    }
    for (int o = 16; o; o >>= 1) {
        a0 += __shfl_xor_sync(0xffffffffu, a0, o);
        a1 += __shfl_xor_sync(0xffffffffu, a1, o);
    }
    float deg = (float)(end - row);
    float inv = deg > 0.f ? 1.f / deg : 0.f;
    float m0 = a0 * inv, m1 = a1 * inv;
    float x0 = x[2 * gw], x1 = x[2 * gw + 1];
    int d0 = lane, d1 = lane + 32;
    float o0 = Wl[d0 * 2] * m0 + Wl[d0 * 2 + 1] * m1 + bl[d0] + Wr[d0 * 2] * x0 + Wr[d0 * 2 + 1] * x1;
    float o1 = Wl[d1 * 2] * m0 + Wl[d1 * 2 + 1] * m1 + bl[d1] + Wr[d1 * 2] * x0 + Wr[d1 * 2 + 1] * x1;
    o0 = fmaxf(o0, 0.f); o1 = fmaxf(o1, 0.f);
    d_hA[gw * 64 + d0] = o0;
    d_hA[gw * 64 + d1] = o1;
    float w0 = wp[d0], w1 = wp[d1];
    float sd = o0 * w0 + o1 * w1, nw = w0 * w0 + w1 * w1;
    for (int o = 16; o; o >>= 1) {
        sd += __shfl_xor_sync(0xffffffffu, sd, o);
        nw += __shfl_xor_sync(0xffffffffu, nw, o);
    }
    if (lane == 0) d_score[gw] = tanhf(sd * rsqrtf(nw));
}

// ---------------- radix select (per-graph exact k-th largest) ----------------
__global__ void select_kernel(int m, int k) {
    __shared__ unsigned hist[256];
    __shared__ unsigned s_pref;
    __shared__ int s_rem;
    int b = blockIdx.x, t = threadIdx.x;
    int base = b * m;
    if (t == 0) { s_pref = 0u; s_rem = k; }
    __syncthreads();
    for (int p = 3; p >= 0; p--) {
        hist[t] = 0;
        __syncthreads();
        unsigned pref = s_pref;
        int hs = (p + 1) * 8;
        for (int i = t; i < m; i += 256) {
            unsigned u = fkey(d_score[base + i]);
            bool cand = (p == 3) || ((u >> hs) == (pref >> hs));
            if (cand) atomicAdd(&hist[(u >> (p * 8)) & 255], 1u);
        }
        __syncthreads();
        if (t == 0) {
            int rem = s_rem;
            unsigned c = 0;
            for (int bb = 255; bb >= 0; bb--) {
                if (c + hist[bb] >= (unsigned)rem) {
                    s_pref = pref | ((unsigned)bb << (p * 8));
                    s_rem = rem - (int)c;
                    break;
                }
                c += hist[bb];
            }
        }
        __syncthreads();
    }
    if (t == 0) {
        d_thresh[b] = s_pref;
        d_quota[b] = s_rem;
        d_ctr[b] = 0;
        d_eq[b] = 0;
    }
}

__global__ void compact_kernel(int shift, int k, int flip) {
    int c = blockIdx.x * blockDim.x + threadIdx.x;
    int b = c >> shift;
    unsigned u = fkey(d_score[c]);
    unsigned th = d_thresh[b];
    const int* oldm = flip ? d_c2oB : d_c2oA;
    int* newm = flip ? d_c2oA : d_c2oB;
    bool keep = u > th;
    if (!keep && u == th) keep = (atomicAdd(&d_eq[b], 1) < d_quota[b]);
    int orig = oldm[c];
    if (keep) {
        int slot = atomicAdd(&d_ctr[b], 1);
        int nc = b * k + slot;
        newm[nc] = orig;
        d_o2c[orig] = nc;
        d_oldidx[nc] = c;
    } else {
        d_o2c[orig] = -1;
    }
}

// ---------------- pool copy + fused readout partials ----------------
__global__ void __launch_bounds__(256) copyro_kernel(int k, int stage) {
    __shared__ float sv[8][64];
    int gw = (blockIdx.x * blockDim.x + threadIdx.x) >> 5;
    int w = (threadIdx.x >> 5);
    int lane = threadIdx.x & 31;
    int oldc = d_oldidx[gw];
    float v = d_score[oldc];
    float v0 = d_hA[oldc * 64 + lane] * v;
    float v1 = d_hA[oldc * 64 + lane + 32] * v;
    d_hB[gw * 64 + lane] = v0;
    d_hB[gw * 64 + lane + 32] = v1;
    sv[w][lane] = v0;
    sv[w][lane + 32] = v1;
    __syncthreads();
    int t = threadIdx.x;
    if (t < 64) {
        float mx = sv[0][t], sm = 0.f;
        #pragma unroll
        for (int ww = 0; ww < 8; ww++) {
            float f = sv[ww][t];
            mx = fmaxf(mx, f);
            sm += f;
        }
        int b = (blockIdx.x * 8) / k;
        int off = stage * GB * 64 + b * 64 + t;
        atomicMax(&d_romax[off], fkey(mx));
        atomicAdd(&d_rosum[off], sm);
    }
}

// ---------------- SAGE2 aggregation: mean of live neighbors -> d_xw ----------------
__global__ void __launch_bounds__(256) sage_agg_kernel(int M, int sel) {
    int gw = (blockIdx.x * blockDim.x + threadIdx.x) >> 5;
    if (gw >= M) return;
    int lane = threadIdx.x & 31;
    const int* c2o = sel ? d_c2oB : d_c2oA;
    int o = c2o[gw];
    int row = d_rowptr[o], end = d_rowptr[o + 1];
    float a0 = 0.f, a1 = 0.f;
    int cnt = 0;
    for (int base = row; base < end; base += 32) {
        int e = base + lane;
        int sc = -1;
        if (e < end) sc = d_o2c[d_csr_src[e]];
        int nb = min(32, end - base);
        for (int j = 0; j < nb; j++) {
            int scj = __shfl_sync(0xffffffffu, sc, j);
            if (scj >= 0) {
                cnt++;
                a0 += d_hB[scj * 64 + lane];
                a1 += d_hB[scj * 64 + lane + 32];
            }
        }
    }
    float invc = cnt ? 1.f / (float)cnt : 0.f;
    d_xw[gw * 64 + lane] = a0 * invc;
    d_xw[gw * 64 + lane + 32] = a1 * invc;
}

// ---------------- SAGE2 transform: tiled, 4 nodes/warp, smem weights ----------------
__global__ void __launch_bounds__(256) sage_tf_kernel(int M, const float* __restrict__ bl,
                                                      const float* __restrict__ wp) {
    __shared__ float sWl[4096];
    __shared__ float sWr[4096];
    int t = threadIdx.x;
    for (int i = t; i < 4096; i += 256) {
        sWl[i] = d_WT[0][i];
        sWr[i] = d_WT[1][i];
    }
    __syncthreads();
    int lane = t & 31;
    int gw = (blockIdx.x * 8) + (t >> 5);
    int n0 = gw * 4;
    float mA[4], mB[4], hA[4], hB[4], o0[4], o1[4];
    #pragma unroll
    for (int q = 0; q < 4; q++) {
        int n = n0 + q;
        mA[q] = d_xw[n * 64 + lane];
        mB[q] = d_xw[n * 64 + lane + 32];
        hA[q] = d_hB[n * 64 + lane];
        hB[q] = d_hB[n * 64 + lane + 32];
        o0[q] = 0.f; o1[q] = 0.f;
    }
    #pragma unroll 4
    for (int j = 0; j < 32; j++) {
        float wl0 = sWl[j * 64 + lane], wl1 = sWl[j * 64 + lane + 32];
        float wr0 = sWr[j * 64 + lane], wr1 = sWr[j * 64 + lane + 32];
        #pragma unroll
        for (int q = 0; q < 4; q++) {
            float mj = __shfl_sync(0xffffffffu, mA[q], j);
            float hj = __shfl_sync(0xffffffffu, hA[q], j);
            o0[q] += wl0 * mj + wr0 * hj;
            o1[q] += wl1 * mj + wr1 * hj;
        }
    }
    #pragma unroll 4
    for (int j = 32; j < 64; j++) {
        float wl0 = sWl[j * 64 + lane], wl1 = sWl[j * 64 + lane + 32];
        float wr0 = sWr[j * 64 + lane], wr1 = sWr[j * 64 + lane + 32];
        #pragma unroll
        for (int q = 0; q < 4; q++) {
            float mj = __shfl_sync(0xffffffffu, mB[q], j - 32);
            float hj = __shfl_sync(0xffffffffu, hB[q], j - 32);
            o0[q] += wl0 * mj + wr0 * hj;
            o1[q] += wl1 * mj + wr1 * hj;
        }
    }
    float b0 = bl[lane], b1 = bl[lane + 32];
    float w0 = wp[lane], w1 = wp[lane + 32];
    float nw = w0 * w0 + w1 * w1;
    for (int o = 16; o; o >>= 1) nw += __shfl_xor_sync(0xffffffffu, nw, o);
    float rn = rsqrtf(nw);
    #pragma unroll
    for (int q = 0; q < 4; q++) {
        int n = n0 + q;
        float r0 = fmaxf(o0[q] + b0, 0.f);
        float r1 = fmaxf(o1[q] + b1, 0.f);
        d_hA[n * 64 + lane] = r0;
        d_hA[n * 64 + lane + 32] = r1;
        float sd = r0 * w0 + r1 * w1;
        for (int o = 16; o; o >>= 1) sd += __shfl_xor_sync(0xffffffffu, sd, o);
        if (lane == 0) d_score[n] = tanhf(sd * rn);
    }
}

// ---------------- GCN xw transform (tiled) + fused degree ----------------
__global__ void __launch_bounds__(256) xwdeg_kernel(int M, int slot, int sel) {
    __shared__ float sW[4096];
    int t = threadIdx.x;
    for (int i = t; i < 4096; i += 256) sW[i] = d_WT[slot][i];
    __syncthreads();
    int lane = t & 31;
    int gw = (blockIdx.x * 8) + (t >> 5);
    int n0 = gw * 4;
    float hA[4], hB[4], o0[4], o1[4];
    #pragma unroll
    for (int q = 0; q < 4; q++) {
        int n = n0 + q;
        hA[q] = d_hB[n * 64 + lane];
        hB[q] = d_hB[n * 64 + lane + 32];
        o0[q] = 0.f; o1[q] = 0.f;
    }
    #pragma unroll 4
    for (int j = 0; j < 32; j++) {
        float w0 = sW[j * 64 + lane], w1 = sW[j * 64 + lane + 32];
        #pragma unroll
        for (int q = 0; q < 4; q++) {
            float hj = __shfl_sync(0xffffffffu, hA[q], j);
            o0[q] += w0 * hj;
            o1[q] += w1 * hj;
        }
    }
    #pragma unroll 4
    for (int j = 32; j < 64; j++) {
        float w0 = sW[j * 64 + lane], w1 = sW[j * 64 + lane + 32];
        #pragma unroll
        for (int q = 0; q < 4; q++) {
            float hj = __shfl_sync(0xffffffffu, hB[q], j - 32);
            o0[q] += w0 * hj;
            o1[q] += w1 * hj;
        }
    }
    const int* c2o = sel ? d_c2oB : d_c2oA;
    #pragma unroll
    for (int q = 0; q < 4; q++) {
        int n = n0 + q;
        d_xw[n * 64 + lane] = o0[q];
        d_xw[n * 64 + lane + 32] = o1[q];
        // fused degree: count live neighbors of node n
        int o = c2o[n];
        int row = d_rowptr[o], end = d_rowptr[o + 1];
        int cnt = 0;
        for (int base = row; base < end; base += 32) {
            int e = base + lane;
            bool live = false;
            if (e < end) live = (d_o2c[d_csr_src[e]] >= 0);
            cnt += __popc(__ballot_sync(0xffffffffu, live));
        }
        if (lane == 0) d_dis[n] = rsqrtf(1.f + (float)cnt);
    }
}

// ---------------- GCN aggregation + epilogue ----------------
__global__ void __launch_bounds__(256) gcn_kernel(int M, const float* __restrict__ bias,
                                                  const float* __restrict__ wp, int sel) {
    int gw = (blockIdx.x * blockDim.x + threadIdx.x) >> 5;
    if (gw >= M) return;
    int lane = threadIdx.x & 31;
    const int* c2o = sel ? d_c2oB : d_c2oA;
    int o = c2o[gw];
    float dd = d_dis[gw];
    int row = d_rowptr[o], end = d_rowptr[o + 1];
    int d0 = lane, d1 = lane + 32;
    float a0 = 0.f, a1 = 0.f;
    for (int base = row; base < end; base += 32) {
        int e = base + lane;
        int sc = -1;
        float ds = 0.f;
        if (e < end) {
            sc = d_o2c[d_csr_src[e]];
            if (sc >= 0) ds = d_dis[sc];
        }
        int nb = min(32, end - base);
        for (int j = 0; j < nb; j++) {
            int scj = __shfl_sync(0xffffffffu, sc, j);
            float dsj = __shfl_sync(0xffffffffu, ds, j);
            if (scj >= 0) {
                a0 += d_xw[scj * 64 + d0] * dsj;
                a1 += d_xw[scj * 64 + d1] * dsj;
            }
        }
    }
    a0 *= dd; a1 *= dd;
    float o0 = a0 + d_xw[gw * 64 + d0] * dd * dd + bias[d0];
    float o1 = a1 + d_xw[gw * 64 + d1] * dd * dd + bias[d1];
    o0 = fmaxf(o0, 0.f); o1 = fmaxf(o1, 0.f);
    d_hA[gw * 64 + d0] = o0;
    d_hA[gw * 64 + d1] = o1;
    float w0 = wp[d0], w1 = wp[d1];
    float sd = o0 * w0 + o1 * w1, nw = w0 * w0 + w1 * w1;
    for (int s = 16; s; s >>= 1) {
        sd += __shfl_xor_sync(0xffffffffu, sd, s);
        nw += __shfl_xor_sync(0xffffffffu, nw, s);
    }
    if (lane == 0) d_score[gw] = tanhf(sd * rsqrtf(nw));
}

// ---------------- final MLP + softmax ----------------
__global__ void __launch_bounds__(1024, 1) mlp_kernel(const float* __restrict__ Wa, const float* __restrict__ ba,
                           const float* __restrict__ Wb, const float* __restrict__ bb,
                           const float* __restrict__ Wc, const float* __restrict__ bc,
                           float* __restrict__ out) {
    __shared__ float zs[1024];
    __shared__ float za[1024];
    __shared__ float zb[512];
    __shared__ float zc[2048];
    int t = threadIdx.x;
    {
        int b = t >> 7, d = t & 127;
        const float invk[4] = {1.f / 8192.f, 1.f / 4096.f, 1.f / 2048.f, 1.f / 1024.f};
        float acc = 0.f;
        if (d < 64) {
            #pragma unroll
            for (int st = 0; st < 4; st++)
                acc += unfkey(d_romax[st * GB * 64 + b * 64 + d]);
        } else {
            #pragma unroll
            for (int st = 0; st < 4; st++)
                acc += d_rosum[st * GB * 64 + b * 64 + (d - 64)] * invk[st];
        }
        zs[t] = acc;
    }
    __syncthreads();
    {
        int b = t >> 7, o = t & 127;
        float a = ba[o];
        const float* w = Wa + o * 128;
        const float* z = zs + b * 128;
        for (int j = 0; j < 128; j++) a += w[j] * z[j];
        za[t] = fmaxf(a, 0.f);
    }
    __syncthreads();
    if (t < 512) {
        int b = t >> 6, o = t & 63;
        float a = bb[o];
        for (int j = 0; j < 128; j++) a += Wb[o * 128 + j] * za[b * 128 + j];
        zb[t] = fmaxf(a, 0.f);
    }
    __syncthreads();
    for (int q = t; q < 2048; q += 1024) {
        int b = q >> 8, o = q & 255;
        float a = bc[o];
        for (int j = 0; j < 64; j++) a += Wc[o * 64 + j] * zb[b * 64 + j];
        zc[q] = a;
    }
    __syncthreads();
    int w = t >> 5, lane = t & 31;
    if (w < 8) {
        float mx = -3.4e38f;
        for (int i = lane; i < 256; i += 32) mx = fmaxf(mx, zc[w * 256 + i]);
        for (int o = 16; o; o >>= 1) mx = fmaxf(mx, __shfl_xor_sync(0xffffffffu, mx, o));
        float s = 0.f;
        for (int i = lane; i < 256; i += 32) {
            float e = expf(zc[w * 256 + i] - mx);
            zc[w * 256 + i] = e;
            s += e;
        }
        for (int o = 16; o; o >>= 1) s += __shfl_xor_sync(0xffffffffu, s, o);
        float inv = 1.f / s;
        for (int i = lane; i < 256; i += 32) out[w * 256 + i] = zc[w * 256 + i] * inv;
    }
}

// ---------------- launch ----------------
extern "C" void kernel_launch(void* const* d_in, const int* in_sizes, int n_in,
                              void* d_out, int out_size) {
    const float* x = (const float*)d_in[0];
    const int* ei = (const int*)d_in[1];
    const int* src = ei;
    const int* dst = ei + EE;
    const float* Wl1 = (const float*)d_in[2];
    const float* bl1 = (const float*)d_in[3];
    const float* Wr1 = (const float*)d_in[4];
    const float* Wl2 = (const float*)d_in[5];
    const float* bl2 = (const float*)d_in[6];
    const float* Wr2 = (const float*)d_in[7];
    const float* W4  = (const float*)d_in[8];
    const float* b4  = (const float*)d_in[9];
    const float* W5  = (const float*)d_in[10];
    const float* b5  = (const float*)d_in[11];
    const float* wp1 = (const float*)d_in[12];
    const float* wp2 = (const float*)d_in[13];
    const float* wp4 = (const float*)d_in[14];
    const float* wp5 = (const float*)d_in[15];
    const float* Wa  = (const float*)d_in[16];
    const float* ba  = (const float*)d_in[17];
    const float* Wb  = (const float*)d_in[18];
    const float* bb  = (const float*)d_in[19];
    const float* Wc  = (const float*)d_in[20];
    const float* bc  = (const float*)d_in[21];
    float* out = (float*)d_out;

    // CSR build
    init_kernel<<<NN / 256, 256>>>();
    hist_kernel<<<EE / 256, 256>>>(dst);
    scan1_kernel<<<128, 1024>>>();
    scan2_kernel<<<1, 128>>>();
    scan3_kernel<<<NN / 256, 256>>>();
    scatter_kernel<<<EE / 256, 256>>>(src, dst);
    transpose_all_kernel<<<64, 256>>>(Wl2, Wr2, W4, W5);

    // stage 1: SAGE1 on all N nodes, pool 16384 -> 8192
    conv1_kernel<<<NN / 8, 256>>>(x, Wl1, bl1, Wr1, wp1);
    select_kernel<<<GB, 256>>>(16384, 8192);
    compact_kernel<<<(GB * 16384) / 256, 256>>>(14, 8192, 0);
    copyro_kernel<<<(GB * 8192) / 8, 256>>>(8192, 0);

    // stage 2: SAGE2 on 65536 nodes, pool 8192 -> 4096
    sage_agg_kernel<<<65536 / 8, 256>>>(65536, 1);
    sage_tf_kernel<<<65536 / 32, 256>>>(65536, bl2, wp2);
    select_kernel<<<GB, 256>>>(8192, 4096);
    compact_kernel<<<(GB * 8192) / 256, 256>>>(13, 4096, 1);
    copyro_kernel<<<(GB * 4096) / 8, 256>>>(4096, 1);

    // stage 3: GCN on 32768 nodes, pool 4096 -> 2048
    xwdeg_kernel<<<32768 / 32, 256>>>(32768, 2, 0);
    gcn_kernel<<<32768 / 8, 256>>>(32768, b4, wp4, 0);
    select_kernel<<<GB, 256>>>(4096, 2048);
    compact_kernel<<<(GB * 4096) / 256, 256>>>(12, 2048, 0);
    copyro_kernel<<<(GB * 2048) / 8, 256>>>(2048, 2);

    // stage 4: GCN on 16384 nodes, pool 2048 -> 1024
    xwdeg_kernel<<<16384 / 32, 256>>>(16384, 3, 1);
    gcn_kernel<<<16384 / 8, 256>>>(16384, b5, wp5, 1);
    select_kernel<<<GB, 256>>>(2048, 1024);
    compact_kernel<<<(GB * 2048) / 256, 256>>>(11, 1024, 1);
    copyro_kernel<<<(GB * 1024) / 8, 256>>>(1024, 3);

    // final MLP + softmax
    mlp_kernel<<<1, 1024>>>(Wa, ba, Wb, bb, Wc, bc, out);
}

// round 4
// speedup vs baseline: 1.1109x; 1.0004x over previous
#include <cuda_runtime.h>

#define NN 131072
#define EE 2097152
#define GB 8
#define CWD 64

// ---------------- static device scratch ----------------
__device__ int d_cnt[NN];
__device__ int d_rowptr[NN + 1];
__device__ int d_cursor[NN];
__device__ int d_csr_src[EE];
__device__ int d_blocksums[128];
__device__ float d_hA[NN * CWD];
__device__ float d_hB[NN * CWD];
__device__ float d_xw[NN * CWD];
__device__ float d_score[NN];
__device__ float d_dis[NN];
__device__ int d_c2oA[NN];
__device__ int d_c2oB[NN];
__device__ int d_o2c[NN];
__device__ int d_oldidx[NN];
__device__ unsigned d_thresh[GB];
__device__ int d_quota[GB];
__device__ int d_ctr[GB];
__device__ int d_eq[GB];
__device__ unsigned d_romax[4 * GB * CWD];  // fkey-encoded per-dim max
__device__ float d_rosum[4 * GB * CWD];     // per-dim sum
__device__ float d_WT[4][CWD * CWD];        // transposed Wl2, Wr2, W4, W5

__device__ __forceinline__ unsigned fkey(float f) {
    unsigned b = __float_as_uint(f);
    return (b & 0x80000000u) ? ~b : (b | 0x80000000u);
}
__device__ __forceinline__ float unfkey(unsigned u) {
    unsigned b = (u & 0x80000000u) ? (u & 0x7fffffffu) : ~u;
    return __uint_as_float(b);
}

// ---------------- CSR build + weight transpose ----------------
__global__ void init_kernel(const float* __restrict__ Wl2, const float* __restrict__ Wr2,
                            const float* __restrict__ W4, const float* __restrict__ W5) {
    int i = blockIdx.x * blockDim.x + threadIdx.x;
    if (i < NN) { d_cnt[i] = 0; d_c2oA[i] = i; }
    if (i < 4 * GB * CWD) { d_romax[i] = 0u; d_rosum[i] = 0.f; }
    if (i < 4 * 4096) {
        int slot = i >> 12;
        int j = i & 4095;
        const float* W = slot == 0 ? Wl2 : slot == 1 ? Wr2 : slot == 2 ? W4 : W5;
        int r = j >> 6, c = j & 63;
        d_WT[slot][c * 64 + r] = W[j];
    }
}

__global__ void hist_kernel(const int* __restrict__ dst) {
    int e = blockIdx.x * blockDim.x + threadIdx.x;
    if (e < EE) atomicAdd(&d_cnt[dst[e]], 1);
}

__global__ void __launch_bounds__(1024, 1) scan1_kernel() {
    __shared__ int s[1024];
    int t = threadIdx.x, i = blockIdx.x * 1024 + t;
    int v = d_cnt[i];
    s[t] = v; __syncthreads();
    for (int off = 1; off < 1024; off <<= 1) {
        int tmp = (t >= off) ? s[t - off] : 0;
        __syncthreads();
        s[t] += tmp;
        __syncthreads();
    }
    d_rowptr[i] = s[t] - v;
    if (t == 1023) d_blocksums[blockIdx.x] = s[t];
}

__global__ void scan2_kernel() {
    __shared__ int s[128];
    int t = threadIdx.x;
    int v = d_blocksums[t];
    s[t] = v; __syncthreads();
    for (int off = 1; off < 128; off <<= 1) {
        int tmp = (t >= off) ? s[t - off] : 0;
        __syncthreads();
        s[t] += tmp;
        __syncthreads();
    }
    d_blocksums[t] = s[t] - v;  // exclusive
}

__global__ void scan3_kernel() {
    int i = blockIdx.x * blockDim.x + threadIdx.x;
    if (i < NN) {
        int r = d_rowptr[i] + d_blocksums[i >> 10];
        d_rowptr[i] = r;
        d_cursor[i] = r;
        if (i == 0) d_rowptr[NN] = EE;
    }
}

__global__ void scatter_kernel(const int* __restrict__ src, const int* __restrict__ dst) {
    int e = blockIdx.x * blockDim.x + threadIdx.x;
    if (e < EE) {
        int p = atomicAdd(&d_cursor[dst[e]], 1);
        d_csr_src[p] = src[e];
    }
}

// ---------------- conv1: SAGE (2 -> 64), warp per node, all edges alive ----------------
__global__ void conv1_kernel(const float* __restrict__ x,
                             const float* __restrict__ Wl, const float* __restrict__ bl,
                             const float* __restrict__ Wr, const float* __restrict__ wp) {
    int gw = (blockIdx.x * blockDim.x + threadIdx.x) >> 5;
    if (gw >= NN) return;
    int lane = threadIdx.x & 31;
    const float2* x2 = (const float2*)x;
    int row = d_rowptr[gw], end = d_rowptr[gw + 1];
    float a0 = 0.f, a1 = 0.f;
    for (int e = row + lane; e < end; e += 32) {
        int s = d_csr_src[e];
        float2 v = x2[s];
        a0 += v.x;
        a1 += v.y;
    }
    for (int o = 16; o; o >>= 1) {
        a0 += __shfl_xor_sync(0xffffffffu, a0, o);
        a1 += __shfl_xor_sync(0xffffffffu, a1, o);
    }
    float deg = (float)(end - row);
    float inv = deg > 0.f ? 1.f / deg : 0.f;
    float m0 = a0 * inv, m1 = a1 * inv;
    float2 xv = x2[gw];
    int d0 = lane, d1 = lane + 32;
    float o0 = Wl[d0 * 2] * m0 + Wl[d0 * 2 + 1] * m1 + bl[d0] + Wr[d0 * 2] * xv.x + Wr[d0 * 2 + 1] * xv.y;
    float o1 = Wl[d1 * 2] * m0 + Wl[d1 * 2 + 1] * m1 + bl[d1] + Wr[d1 * 2] * xv.x + Wr[d1 * 2 + 1] * xv.y;
    o0 = fmaxf(o0, 0.f); o1 = fmaxf(o1, 0.f);
    d_hA[gw * 64 + d0] = o0;
    d_hA[gw * 64 + d1] = o1;
    float w0 = wp[d0], w1 = wp[d1];
    float sd = o0 * w0 + o1 * w1, nw = w0 * w0 + w1 * w1;
    for (int o = 16; o; o >>= 1) {
        sd += __shfl_xor_sync(0xffffffffu, sd, o);
        nw += __shfl_xor_sync(0xffffffffu, nw, o);
    }
    if (lane == 0) d_score[gw] = tanhf(sd * rsqrtf(nw));
}

// ---------------- radix select (per-graph exact k-th largest) ----------------
__global__ void __launch_bounds__(1024, 1) select_kernel(int m, int k) {
    __shared__ unsigned hist[256];
    __shared__ unsigned s_pref;
    __shared__ int s_rem;
    int b = blockIdx.x, t = threadIdx.x;
    int base = b * m;
    if (t == 0) { s_pref = 0u; s_rem = k; }
    __syncthreads();
    for (int p = 3; p >= 0; p--) {
        if (t < 256) hist[t] = 0;
        __syncthreads();
        unsigned pref = s_pref;
        int hs = (p + 1) * 8;
        for (int i = t; i < m; i += 1024) {
            unsigned u = fkey(d_score[base + i]);
            bool cand = (p == 3) || ((u >> hs) == (pref >> hs));
            if (cand) atomicAdd(&hist[(u >> (p * 8)) & 255], 1u);
        }
        __syncthreads();
        if (t == 0) {
            int rem = s_rem;
            unsigned c = 0;
            for (int bb = 255; bb >= 0; bb--) {
                if (c + hist[bb] >= (unsigned)rem) {
                    s_pref = pref | ((unsigned)bb << (p * 8));
                    s_rem = rem - (int)c;
                    break;
                }
                c += hist[bb];
            }
        }
        __syncthreads();
    }
    if (t == 0) {
        d_thresh[b] = s_pref;
        d_quota[b] = s_rem;
        d_ctr[b] = 0;
        d_eq[b] = 0;
    }
}

__global__ void compact_kernel(int shift, int k, int flip) {
    int c = blockIdx.x * blockDim.x + threadIdx.x;
    int b = c >> shift;
    unsigned u = fkey(d_score[c]);
    unsigned th = d_thresh[b];
    const int* oldm = flip ? d_c2oB : d_c2oA;
    int* newm = flip ? d_c2oA : d_c2oB;
    bool keep = u > th;
    if (!keep && u == th) keep = (atomicAdd(&d_eq[b], 1) < d_quota[b]);
    int orig = oldm[c];
    if (keep) {
        int slot = atomicAdd(&d_ctr[b], 1);
        int nc = b * k + slot;
        newm[nc] = orig;
        d_o2c[orig] = nc;
        d_oldidx[nc] = c;
    } else {
        d_o2c[orig] = -1;
    }
}

// ---------------- pool copy + fused readout partials ----------------
__global__ void __launch_bounds__(256) copyro_kernel(int k, int stage) {
    __shared__ float sv[8][64];
    int gw = (blockIdx.x * blockDim.x + threadIdx.x) >> 5;
    int w = (threadIdx.x >> 5);
    int lane = threadIdx.x & 31;
    int oldc = d_oldidx[gw];
    float v = d_score[oldc];
    float2 h = *(const float2*)&d_hA[oldc * 64 + 2 * lane];
    float v0 = h.x * v, v1 = h.y * v;
    *(float2*)&d_hB[gw * 64 + 2 * lane] = make_float2(v0, v1);
    sv[w][2 * lane] = v0;
    sv[w][2 * lane + 1] = v1;
    __syncthreads();
    int t = threadIdx.x;
    if (t < 64) {
        float mx = sv[0][t], sm = 0.f;
        #pragma unroll
        for (int ww = 0; ww < 8; ww++) {
            float f = sv[ww][t];
            mx = fmaxf(mx, f);
            sm += f;
        }
        int b = (blockIdx.x * 8) / k;
        int off = stage * GB * 64 + b * 64 + t;
        atomicMax(&d_romax[off], fkey(mx));
        atomicAdd(&d_rosum[off], sm);
    }
}

// ---------------- SAGE2 fused: agg (ballot-live, float2) + tiled transform ----------------
__global__ void __launch_bounds__(256) sage_fused_kernel(const float* __restrict__ bl,
                                                         const float* __restrict__ wp) {
    __shared__ float sWl[4096];
    __shared__ float sWr[4096];
    __shared__ float sm_m[32][64];
    int t = threadIdx.x;
    for (int i = t; i < 4096; i += 256) {
        sWl[i] = d_WT[0][i];
        sWr[i] = d_WT[1][i];
    }
    int lane = t & 31;
    int w = t >> 5;
    int nblock = blockIdx.x * 32;  // 32 nodes per block

    // phase A: aggregation, warp w handles nodes nblock + w*4 + q
    for (int q = 0; q < 4; q++) {
        int n = nblock + w * 4 + q;
        int o = d_c2oB[n];
        int row = d_rowptr[o], end = d_rowptr[o + 1];
        float a0 = 0.f, a1 = 0.f;
        int cnt = 0;
        for (int base = row; base < end; base += 32) {
            int e = base + lane;
            int sc = -1;
            if (e < end) sc = d_o2c[d_csr_src[e]];
            unsigned liveb = __ballot_sync(0xffffffffu, sc >= 0);
            cnt += __popc(liveb);
            while (liveb) {
                int j = __ffs(liveb) - 1;
                liveb &= liveb - 1;
                int scj = __shfl_sync(0xffffffffu, sc, j);
                float2 v = *(const float2*)&d_hB[scj * 64 + 2 * lane];
                a0 += v.x;
                a1 += v.y;
            }
        }
        float invc = cnt ? 1.f / (float)cnt : 0.f;
        sm_m[w * 4 + q][2 * lane] = a0 * invc;
        sm_m[w * 4 + q][2 * lane + 1] = a1 * invc;
    }
    __syncthreads();

    // phase B: transform, warp w handles same 4 nodes, dims {lane, lane+32}
    int n0 = nblock + w * 4;
    float mA[4], mB[4], hA[4], hB[4], o0[4], o1[4];
    #pragma unroll
    for (int q = 0; q < 4; q++) {
        int n = n0 + q;
        mA[q] = sm_m[w * 4 + q][lane];
        mB[q] = sm_m[w * 4 + q][lane + 32];
        hA[q] = d_hB[n * 64 + lane];
        hB[q] = d_hB[n * 64 + lane + 32];
        o0[q] = 0.f; o1[q] = 0.f;
    }
    #pragma unroll 4
    for (int j = 0; j < 32; j++) {
        float wl0 = sWl[j * 64 + lane], wl1 = sWl[j * 64 + lane + 32];
        float wr0 = sWr[j * 64 + lane], wr1 = sWr[j * 64 + lane + 32];
        #pragma unroll
        for (int q = 0; q < 4; q++) {
            float mj = __shfl_sync(0xffffffffu, mA[q], j);
            float hj = __shfl_sync(0xffffffffu, hA[q], j);
            o0[q] += wl0 * mj + wr0 * hj;
            o1[q] += wl1 * mj + wr1 * hj;
        }
    }
    #pragma unroll 4
    for (int j = 32; j < 64; j++) {
        float wl0 = sWl[j * 64 + lane], wl1 = sWl[j * 64 + lane + 32];
        float wr0 = sWr[j * 64 + lane], wr1 = sWr[j * 64 + lane + 32];
        #pragma unroll
        for (int q = 0; q < 4; q++) {
            float mj = __shfl_sync(0xffffffffu, mB[q], j - 32);
            float hj = __shfl_sync(0xffffffffu, hB[q], j - 32);
            o0[q] += wl0 * mj + wr0 * hj;
            o1[q] += wl1 * mj + wr1 * hj;
        }
    }
    float b0 = bl[lane], b1 = bl[lane + 32];
    float w0 = wp[lane], w1 = wp[lane + 32];
    float nw = w0 * w0 + w1 * w1;
    for (int o = 16; o; o >>= 1) nw += __shfl_xor_sync(0xffffffffu, nw, o);
    float rn = rsqrtf(nw);
    #pragma unroll
    for (int q = 0; q < 4; q++) {
        int n = n0 + q;
        float r0 = fmaxf(o0[q] + b0, 0.f);
        float r1 = fmaxf(o1[q] + b1, 0.f);
        d_hA[n * 64 + lane] = r0;
        d_hA[n * 64 + lane + 32] = r1;
        float sd = r0 * w0 + r1 * w1;
        for (int o = 16; o; o >>= 1) sd += __shfl_xor_sync(0xffffffffu, sd, o);
        if (lane == 0) d_score[n] = tanhf(sd * rn);
    }
}

// ---------------- GCN xw transform (tiled) + fused degree ----------------
__global__ void __launch_bounds__(256) xwdeg_kernel(int M, int slot, int sel) {
    __shared__ float sW[4096];
    int t = threadIdx.x;
    for (int i = t; i < 4096; i += 256) sW[i] = d_WT[slot][i];
    __syncthreads();
    int lane = t & 31;
    int gw = (blockIdx.x * 8) + (t >> 5);
    int n0 = gw * 4;
    float hA[4], hB[4], o0[4], o1[4];
    #pragma unroll
    for (int q = 0; q < 4; q++) {
        int n = n0 + q;
        hA[q] = d_hB[n * 64 + lane];
        hB[q] = d_hB[n * 64 + lane + 32];
        o0[q] = 0.f; o1[q] = 0.f;
    }
    #pragma unroll 4
    for (int j = 0; j < 32; j++) {
        float w0 = sW[j * 64 + lane], w1 = sW[j * 64 + lane + 32];
        #pragma unroll
        for (int q = 0; q < 4; q++) {
            float hj = __shfl_sync(0xffffffffu, hA[q], j);
            o0[q] += w0 * hj;
            o1[q] += w1 * hj;
        }
    }
    #pragma unroll 4
    for (int j = 32; j < 64; j++) {
        float w0 = sW[j * 64 + lane], w1 = sW[j * 64 + lane + 32];
        #pragma unroll
        for (int q = 0; q < 4; q++) {
            float hj = __shfl_sync(0xffffffffu, hB[q], j - 32);
            o0[q] += w0 * hj;
            o1[q] += w1 * hj;
        }
    }
    const int* c2o = sel ? d_c2oB : d_c2oA;
    #pragma unroll
    for (int q = 0; q < 4; q++) {
        int n = n0 + q;
        d_xw[n * 64 + lane] = o0[q];
        d_xw[n * 64 + lane + 32] = o1[q];
        // fused degree: count live neighbors of node n
        int o = c2o[n];
        int row = d_rowptr[o], end = d_rowptr[o + 1];
        int cnt = 0;
        for (int base = row; base < end; base += 32) {
            int e = base + lane;
            bool live = false;
            if (e < end) live = (d_o2c[d_csr_src[e]] >= 0);
            cnt += __popc(__ballot_sync(0xffffffffu, live));
        }
        if (lane == 0) d_dis[n] = rsqrtf(1.f + (float)cnt);
    }
}

// ---------------- GCN aggregation + epilogue (ballot-live, float2) ----------------
__global__ void __launch_bounds__(256) gcn_kernel(int M, const float* __restrict__ bias,
                                                  const float* __restrict__ wp, int sel) {
    int gw = (blockIdx.x * blockDim.x + threadIdx.x) >> 5;
    if (gw >= M) return;
    int lane = threadIdx.x & 31;
    const int* c2o = sel ? d_c2oB : d_c2oA;
    int o = c2o[gw];
    float dd = d_dis[gw];
    int row = d_rowptr[o], end = d_rowptr[o + 1];
    float a0 = 0.f, a1 = 0.f;
    for (int base = row; base < end; base += 32) {
        int e = base + lane;
        int sc = -1;
        float ds = 0.f;
        if (e < end) {
            sc = d_o2c[d_csr_src[e]];
            if (sc >= 0) ds = d_dis[sc];
        }
        unsigned liveb = __ballot_sync(0xffffffffu, sc >= 0);
        while (liveb) {
            int j = __ffs(liveb) - 1;
            liveb &= liveb - 1;
            int scj = __shfl_sync(0xffffffffu, sc, j);
            float dsj = __shfl_sync(0xffffffffu, ds, j);
            float2 v = *(const float2*)&d_xw[scj * 64 + 2 * lane];
            a0 += v.x * dsj;
            a1 += v.y * dsj;
        }
    }
    a0 *= dd; a1 *= dd;
    float2 self = *(const float2*)&d_xw[gw * 64 + 2 * lane];
    float o0 = a0 + self.x * dd * dd + bias[2 * lane];
    float o1 = a1 + self.y * dd * dd + bias[2 * lane + 1];
    o0 = fmaxf(o0, 0.f); o1 = fmaxf(o1, 0.f);
    *(float2*)&d_hA[gw * 64 + 2 * lane] = make_float2(o0, o1);
    float w0 = wp[2 * lane], w1 = wp[2 * lane + 1];
    float sd = o0 * w0 + o1 * w1, nw = w0 * w0 + w1 * w1;
    for (int s = 16; s; s >>= 1) {
        sd += __shfl_xor_sync(0xffffffffu, sd, s);
        nw += __shfl_xor_sync(0xffffffffu, nw, s);
    }
    if (lane == 0) d_score[gw] = tanhf(sd * rsqrtf(nw));
}

// ---------------- final MLP + softmax ----------------
__global__ void __launch_bounds__(1024, 1) mlp_kernel(const float* __restrict__ Wa, const float* __restrict__ ba,
                           const float* __restrict__ Wb, const float* __restrict__ bb,
                           const float* __restrict__ Wc, const float* __restrict__ bc,
                           float* __restrict__ out) {
    __shared__ float zs[1024];
    __shared__ float za[1024];
    __shared__ float zb[512];
    __shared__ float zc[2048];
    int t = threadIdx.x;
    {
        int b = t >> 7, d = t & 127;
        const float invk[4] = {1.f / 8192.f, 1.f / 4096.f, 1.f / 2048.f, 1.f / 1024.f};
        float acc = 0.f;
        if (d < 64) {
            #pragma unroll
            for (int st = 0; st < 4; st++)
                acc += unfkey(d_romax[st * GB * 64 + b * 64 + d]);
        } else {
            #pragma unroll
            for (int st = 0; st < 4; st++)
                acc += d_rosum[st * GB * 64 + b * 64 + (d - 64)] * invk[st];
        }
        zs[t] = acc;
    }
    __syncthreads();
    {
        int b = t >> 7, o = t & 127;
        float a = ba[o];
        const float* w = Wa + o * 128;
        const float* z = zs + b * 128;
        for (int j = 0; j < 128; j++) a += w[j] * z[j];
        za[t] = fmaxf(a, 0.f);
    }
    __syncthreads();
    if (t < 512) {
        int b = t >> 6, o = t & 63;
        float a = bb[o];
        for (int j = 0; j < 128; j++) a += Wb[o * 128 + j] * za[b * 128 + j];
        zb[t] = fmaxf(a, 0.f);
    }
    __syncthreads();
    for (int q = t; q < 2048; q += 1024) {
        int b = q >> 8, o = q & 255;
        float a = bc[o];
        for (int j = 0; j < 64; j++) a += Wc[o * 64 + j] * zb[b * 64 + j];
        zc[q] = a;
    }
    __syncthreads();
    int w = t >> 5, lane = t & 31;
    if (w < 8) {
        float mx = -3.4e38f;
        for (int i = lane; i < 256; i += 32) mx = fmaxf(mx, zc[w * 256 + i]);
        for (int o = 16; o; o >>= 1) mx = fmaxf(mx, __shfl_xor_sync(0xffffffffu, mx, o));
        float s = 0.f;
        for (int i = lane; i < 256; i += 32) {
            float e = expf(zc[w * 256 + i] - mx);
            zc[w * 256 + i] = e;
            s += e;
        }
        for (int o = 16; o; o >>= 1) s += __shfl_xor_sync(0xffffffffu, s, o);
        float inv = 1.f / s;
        for (int i = lane; i < 256; i += 32) out[w * 256 + i] = zc[w * 256 + i] * inv;
    }
}

// ---------------- launch ----------------
extern "C" void kernel_launch(void* const* d_in, const int* in_sizes, int n_in,
                              void* d_out, int out_size) {
    const float* x = (const float*)d_in[0];
    const int* ei = (const int*)d_in[1];
    const int* src = ei;
    const int* dst = ei + EE;
    const float* Wl1 = (const float*)d_in[2];
    const float* bl1 = (const float*)d_in[3];
    const float* Wr1 = (const float*)d_in[4];
    const float* Wl2 = (const float*)d_in[5];
    const float* bl2 = (const float*)d_in[6];
    const float* Wr2 = (const float*)d_in[7];
    const float* W4  = (const float*)d_in[8];
    const float* b4  = (const float*)d_in[9];
    const float* W5  = (const float*)d_in[10];
    const float* b5  = (const float*)d_in[11];
    const float* wp1 = (const float*)d_in[12];
    const float* wp2 = (const float*)d_in[13];
    const float* wp4 = (const float*)d_in[14];
    const float* wp5 = (const float*)d_in[15];
    const float* Wa  = (const float*)d_in[16];
    const float* ba  = (const float*)d_in[17];
    const float* Wb  = (const float*)d_in[18];
    const float* bb  = (const float*)d_in[19];
    const float* Wc  = (const float*)d_in[20];
    const float* bc  = (const float*)d_in[21];
    float* out = (float*)d_out;

    // CSR build (+ weight transpose folded into init)
    init_kernel<<<NN / 256, 256>>>(Wl2, Wr2, W4, W5);
    hist_kernel<<<EE / 256, 256>>>(dst);
    scan1_kernel<<<128, 1024>>>();
    scan2_kernel<<<1, 128>>>();
    scan3_kernel<<<NN / 256, 256>>>();
    scatter_kernel<<<EE / 256, 256>>>(src, dst);

    // stage 1: SAGE1 on all N nodes, pool 16384 -> 8192
    conv1_kernel<<<NN / 8, 256>>>(x, Wl1, bl1, Wr1, wp1);
    select_kernel<<<GB, 1024>>>(16384, 8192);
    compact_kernel<<<(GB * 16384) / 256, 256>>>(14, 8192, 0);
    copyro_kernel<<<(GB * 8192) / 8, 256>>>(8192, 0);

    // stage 2: SAGE2 on 65536 nodes (fused agg+transform), pool 8192 -> 4096
    sage_fused_kernel<<<65536 / 32, 256>>>(bl2, wp2);
    select_kernel<<<GB, 1024>>>(8192, 4096);
    compact_kernel<<<(GB * 8192) / 256, 256>>>(13, 4096, 1);
    copyro_kernel<<<(GB * 4096) / 8, 256>>>(4096, 1);

    // stage 3: GCN on 32768 nodes, pool 4096 -> 2048
    xwdeg_kernel<<<32768 / 32, 256>>>(32768, 2, 0);
    gcn_kernel<<<32768 / 8, 256>>>(32768, b4, wp4, 0);
    select_kernel<<<GB, 1024>>>(4096, 2048);
    compact_kernel<<<(GB * 4096) / 256, 256>>>(12, 2048, 0);
    copyro_kernel<<<(GB * 2048) / 8, 256>>>(2048, 2);

    // stage 4: GCN on 16384 nodes, pool 2048 -> 1024
    xwdeg_kernel<<<16384 / 32, 256>>>(16384, 3, 1);
    gcn_kernel<<<16384 / 8, 256>>>(16384, b5, wp5, 1);
    select_kernel<<<GB, 1024>>>(2048, 1024);
    compact_kernel<<<(GB * 2048) / 256, 256>>>(11, 1024, 1);
    copyro_kernel<<<(GB * 1024) / 8, 256>>>(1024, 3);

    // final MLP + softmax
    mlp_kernel<<<1, 1024>>>(Wa, ba, Wb, bb, Wc, bc, out);
}